// round 4
// baseline (speedup 1.0000x reference)
#include <cuda_runtime.h>

// Problem constants
#define BB 256
#define TT 2048
// gates = 4*43 = 172 rows (176 padded), hidden = 43
// Layer1: J=56  (ext proj-folded 8 | h @ 8..50 | pad) JC=7  (chunks per j-half)
// Layer2: J=136 (ext 86 + 2 pad   | h @ 88..130| pad) JC=17

using ull = unsigned long long;

__device__ __align__(16) float g_W1[2 * 14 * 176 * 4];
__device__ __align__(16) float g_b1[2 * 172];
__device__ __align__(16) float g_W2[2 * 34 * 176 * 4];
__device__ __align__(16) float g_b2[2 * 172];
__device__ __align__(16) float g_y1[(size_t)BB * TT * 86];
__device__ __align__(16) float g_y2[(size_t)BB * TT * 86];

struct PrepArgs {
    const float* w_proj;   // [43,8]
    const float* b_proj;   // [43]
    const float* wih[4];   // 1f,1b,2f,2b
    const float* whh[4];
    const float* bih[4];
    const float* bhh[4];
};

// Weight layout: W[dir][c][row(176)][4] with j = 4*c + comp; padded rows/cols zero.
__global__ void prep_kernel(PrepArgs A) {
    int id = blockIdx.x * blockDim.x + threadIdx.x;
    int NT = gridDim.x * blockDim.x;

    // ---- Layer-1 weights: 2 x 14 chunks x 176 x 4 (J=56) ----
    const int N1 = 2 * 14 * 176 * 4;
    for (int i = id; i < N1; i += NT) {
        int dir = i / (14 * 176 * 4);
        int rem = i % (14 * 176 * 4);
        int c = rem / (176 * 4);
        int row = (rem >> 2) % 176;
        int comp = rem & 3;
        int j = 4 * c + comp;
        float v = 0.f;
        if (row < 172) {
            if (j < 8) {
                float s = 0.f;
                for (int k = 0; k < 43; ++k)
                    s += A.wih[dir][row * 43 + k] * A.w_proj[k * 8 + j];
                v = s;
            } else if (j < 51) {
                v = A.whh[dir][row * 43 + (j - 8)];
            }
        }
        g_W1[i] = v;
    }
    // Layer-1 effective bias: w_ih1 @ b_proj + b_ih + b_hh
    for (int i = id; i < 2 * 172; i += NT) {
        int dir = i / 172, r = i % 172;
        float s = A.bih[dir][r] + A.bhh[dir][r];
        for (int k = 0; k < 43; ++k)
            s += A.wih[dir][r * 43 + k] * A.b_proj[k];
        g_b1[i] = s;
    }

    // ---- Layer-2 weights: 2 x 34 chunks x 176 x 4 (J=136) ----
    const int N2 = 2 * 34 * 176 * 4;
    for (int i = id; i < N2; i += NT) {
        int dir = i / (34 * 176 * 4);
        int rem = i % (34 * 176 * 4);
        int c = rem / (176 * 4);
        int row = (rem >> 2) % 176;
        int comp = rem & 3;
        int j = 4 * c + comp;
        int di = 2 + dir;
        float v = 0.f;
        if (row < 172) {
            if (j < 86)                 v = A.wih[di][row * 86 + j];
            else if (j >= 88 && j < 131) v = A.whh[di][row * 43 + (j - 88)];
        }
        g_W2[i] = v;
    }
    for (int i = id; i < 2 * 172; i += NT) {
        int dir = i / 172, r = i % 172;
        g_b2[i] = A.bih[2 + dir][r] + A.bhh[2 + dir][r];
    }
}

__device__ __forceinline__ float fsig(float x) {
    return __fdividef(1.f, 1.f + __expf(-x));
}
__device__ __forceinline__ float ftanh_(float x) {
    return 2.f * __fdividef(1.f, 1.f + __expf(-2.f * x)) - 1.f;
}
__device__ __forceinline__ void ffma2(ull& d, ull a, ull b) {
    asm("fma.rn.f32x2 %0, %1, %2, %0;" : "+l"(d) : "l"(a), "l"(b));
}
__device__ __forceinline__ float2 unpk(ull v) {
    float2 r;
    asm("mov.b64 {%0, %1}, %2;" : "=f"(r.x), "=f"(r.y) : "l"(v));
    return r;
}

// One block = 4 sequences (batch quad) x one direction. 352 threads.
// tid -> (row = tid>>1 in [0,176), jh = tid&1). Each thread accumulates the
// (even,odd) j-partials of its j-half for all 4 sequences with fma.rn.f32x2;
// halves combined via shfl_xor(1). Weights stream from global (L1-resident).
template <int JC, int J, int HOFF, int INW, int LAYER>
__global__ __launch_bounds__(352) void lstm_kernel(const float* __restrict__ x_in) {
    __shared__ __align__(16) float sV[4][J];    // [seq][j]
    __shared__ __align__(16) float4 sG[176];    // [gate row] = 4 seqs

    const int tid = threadIdx.x;
    const int quad = blockIdx.x >> 1;
    const int dir = blockIdx.x & 1;
    const int b0 = quad * 4;
    const int row = tid >> 1;
    const int jh = tid & 1;

    const float* gWf = (LAYER == 1 ? g_W1 : g_W2);
    const ulonglong2* __restrict__ gw2 =
        (const ulonglong2*)gWf + ((size_t)dir * 2 * JC + jh * JC) * 176 + row;
    const float* gB = (LAYER == 1 ? g_b1 : g_b2) + dir * 172;
    const float bias = (row < 172) ? gB[row] : 0.f;

    const float* in = (LAYER == 1 ? x_in : (const float*)g_y1);
    float* out = (LAYER == 1 ? g_y1 : g_y2);

    // Stagers: 4*INW threads, seq-major coalesced per sequence.
    const int sseq = tid / INW;
    const int sj = tid - sseq * INW;
    const bool stager = (tid < 4 * INW);
    const float* inme = in + (size_t)(b0 + (stager ? sseq : 0)) * TT * INW;

    // Cell/output: threads 0..171 -> (cr = tid>>2, cseq = tid&3)
    const int cr = tid >> 2;
    const int cseq = tid & 3;
    float* outme = out + (size_t)(b0 + cseq) * TT * 86 + dir * 43;
    float c = 0.f;

    // Zero v (padding + h0 = 0)
    for (int i = tid; i < 4 * J; i += 352) ((float*)sV)[i] = 0.f;

    float rin = 0.f;
    if (stager) rin = inme[(size_t)(dir ? TT - 1 : 0) * INW + sj];
    __syncthreads();

    for (int step = 0; step < TT; ++step) {
        const int t = dir ? (TT - 1 - step) : step;

        if (stager) sV[sseq][sj] = rin;
        float rnext = 0.f;
        if (stager && step + 1 < TT) {
            int tn = dir ? (TT - 2 - step) : (step + 1);
            rnext = inme[(size_t)tn * INW + sj];
        }
        __syncthreads();  // A: v (ext input + h) ready

        ull a0 = 0, a1 = 0, a2 = 0, a3 = 0;
#pragma unroll
        for (int q = 0; q < JC; ++q) {
            ulonglong2 w = gw2[q * 176];
            const int jb = (jh * JC + q) * 4;
            ulonglong2 v0 = *(const ulonglong2*)&sV[0][jb];
            ulonglong2 v1 = *(const ulonglong2*)&sV[1][jb];
            ulonglong2 v2 = *(const ulonglong2*)&sV[2][jb];
            ulonglong2 v3 = *(const ulonglong2*)&sV[3][jb];
            ffma2(a0, w.x, v0.x); ffma2(a0, w.y, v0.y);
            ffma2(a1, w.x, v1.x); ffma2(a1, w.y, v1.y);
            ffma2(a2, w.x, v2.x); ffma2(a2, w.y, v2.y);
            ffma2(a3, w.x, v3.x); ffma2(a3, w.y, v3.y);
        }
        float2 p;
        p = unpk(a0); float z0 = p.x + p.y;
        p = unpk(a1); float z1 = p.x + p.y;
        p = unpk(a2); float z2 = p.x + p.y;
        p = unpk(a3); float z3 = p.x + p.y;
        z0 += __shfl_xor_sync(0xffffffffu, z0, 1);
        z1 += __shfl_xor_sync(0xffffffffu, z1, 1);
        z2 += __shfl_xor_sync(0xffffffffu, z2, 1);
        z3 += __shfl_xor_sync(0xffffffffu, z3, 1);

        if (jh == 0 && row < 172) {
            z0 += bias; z1 += bias; z2 += bias; z3 += bias;
            const bool isg = (row >= 86) && (row < 129);  // g gate -> tanh
            float4 g;
            g.x = isg ? ftanh_(z0) : fsig(z0);
            g.y = isg ? ftanh_(z1) : fsig(z1);
            g.z = isg ? ftanh_(z2) : fsig(z2);
            g.w = isg ? ftanh_(z3) : fsig(z3);
            sG[row] = g;
        }
        __syncthreads();  // B: gates ready

        if (tid < 172) {
            const float* gf = (const float*)sG;
            float iv = gf[cr * 4 + cseq];
            float fv = gf[(43 + cr) * 4 + cseq];
            float gv = gf[(86 + cr) * 4 + cseq];
            float ov = gf[(129 + cr) * 4 + cseq];
            c = fv * c + iv * gv;
            float h = ov * ftanh_(c);
            sV[cseq][HOFF + cr] = h;
            outme[(size_t)t * 86 + cr] = h;
        }
        rin = rnext;
    }
}

// ---------------- Dense head: 64 rows per block (35 KB smem) ----------------
__global__ __launch_bounds__(64) void dense_kernel(
    const float* __restrict__ wd1, const float* __restrict__ bd1,
    const float* __restrict__ wd2, const float* __restrict__ bd2,
    const float* __restrict__ wo, const float* __restrict__ bo,
    float* __restrict__ outp) {
    __shared__ __align__(16) float s_w1[30 * 86];
    __shared__ __align__(16) float s_w2[20 * 30];
    __shared__ float s_b1[30], s_b2[20], s_wo[20];
    __shared__ __align__(16) float s_y[64 * 86];

    int tid = threadIdx.x;
    for (int i = tid; i < 30 * 86; i += 64) s_w1[i] = wd1[i];
    for (int i = tid; i < 20 * 30; i += 64) s_w2[i] = wd2[i];
    if (tid < 30) s_b1[tid] = bd1[tid];
    if (tid < 20) { s_b2[tid] = bd2[tid]; s_wo[tid] = wo[tid]; }

    size_t base = (size_t)blockIdx.x * 64;
    for (int i = tid; i < (64 * 86) / 2; i += 64)
        ((float2*)s_y)[i] = ((const float2*)(g_y2 + base * 86))[i];
    __syncthreads();

    const float* v = s_y + tid * 86;
    float h1[30];
#pragma unroll
    for (int k = 0; k < 30; ++k) h1[k] = s_b1[k];
    for (int cc = 0; cc < 86; ++cc) {
        float vv = v[cc];
#pragma unroll
        for (int k = 0; k < 30; ++k) h1[k] = fmaf(s_w1[k * 86 + cc], vv, h1[k]);
    }
    float h2[20];
#pragma unroll
    for (int k = 0; k < 20; ++k) h2[k] = s_b2[k];
#pragma unroll
    for (int cc = 0; cc < 30; ++cc) {
        float vv = fmaxf(h1[cc], 0.f);
#pragma unroll
        for (int k = 0; k < 20; ++k) h2[k] = fmaf(s_w2[k * 30 + cc], vv, h2[k]);
    }
    float o = bo[0];
#pragma unroll
    for (int k = 0; k < 20; ++k) o = fmaf(s_wo[k], fmaxf(h2[k], 0.f), o);
    outp[base + tid] = o;
}

extern "C" void kernel_launch(void* const* d_in, const int* in_sizes, int n_in,
                              void* d_out, int out_size) {
    const float* x = (const float*)d_in[0];
    PrepArgs A;
    A.w_proj = (const float*)d_in[1];
    A.b_proj = (const float*)d_in[2];
    for (int g = 0; g < 4; ++g) {
        A.wih[g] = (const float*)d_in[3 + g * 4 + 0];
        A.whh[g] = (const float*)d_in[3 + g * 4 + 1];
        A.bih[g] = (const float*)d_in[3 + g * 4 + 2];
        A.bhh[g] = (const float*)d_in[3 + g * 4 + 3];
    }
    const float* wd1 = (const float*)d_in[19];
    const float* bd1 = (const float*)d_in[20];
    const float* wd2 = (const float*)d_in[21];
    const float* bd2 = (const float*)d_in[22];
    const float* wo  = (const float*)d_in[23];
    const float* bo  = (const float*)d_in[24];

    prep_kernel<<<64, 256>>>(A);
    lstm_kernel<7, 56, 8, 8, 1><<<128, 352>>>(x);      // layer 1 (proj folded)
    lstm_kernel<17, 136, 88, 86, 2><<<128, 352>>>(nullptr);  // layer 2
    dense_kernel<<<(BB * TT) / 64, 64>>>(wd1, bd1, wd2, bd2, wo, bo, (float*)d_out);
}

// round 5
// speedup vs baseline: 1.3462x; 1.3462x over previous
#include <cuda_runtime.h>

// Problem constants
#define BB 256
#define TT 2048
// gates = 4*43 = 172 rows (176 padded), hidden = 43
// Layer1: J=56  (ext proj-folded 8 | h @ 8..50 | pad) JC=7  (chunks per j-half)
// Layer2: J=136 (ext 86 + 2 pad   | h @ 88..130| pad) JC=17

using ull = unsigned long long;

__device__ __align__(16) float g_W1[2 * 14 * 176 * 4];
__device__ __align__(16) float g_b1[2 * 172];
__device__ __align__(16) float g_W2[2 * 34 * 176 * 4];
__device__ __align__(16) float g_b2[2 * 172];
__device__ __align__(16) float g_y1[(size_t)BB * TT * 86];
__device__ __align__(16) float g_y2[(size_t)BB * TT * 86];

struct PrepArgs {
    const float* w_proj;   // [43,8]
    const float* b_proj;   // [43]
    const float* wih[4];   // 1f,1b,2f,2b
    const float* whh[4];
    const float* bih[4];
    const float* bhh[4];
};

// Weight layout: W[dir][c][row(176)][4] with j = 4*c + comp; padded rows/cols zero.
__global__ void prep_kernel(PrepArgs A) {
    int id = blockIdx.x * blockDim.x + threadIdx.x;
    int NT = gridDim.x * blockDim.x;

    // ---- Layer-1 weights: 2 x 14 chunks x 176 x 4 (J=56) ----
    const int N1 = 2 * 14 * 176 * 4;
    for (int i = id; i < N1; i += NT) {
        int dir = i / (14 * 176 * 4);
        int rem = i % (14 * 176 * 4);
        int c = rem / (176 * 4);
        int row = (rem >> 2) % 176;
        int comp = rem & 3;
        int j = 4 * c + comp;
        float v = 0.f;
        if (row < 172) {
            if (j < 8) {
                float s = 0.f;
                for (int k = 0; k < 43; ++k)
                    s += A.wih[dir][row * 43 + k] * A.w_proj[k * 8 + j];
                v = s;
            } else if (j < 51) {
                v = A.whh[dir][row * 43 + (j - 8)];
            }
        }
        g_W1[i] = v;
    }
    // Layer-1 effective bias: w_ih1 @ b_proj + b_ih + b_hh
    for (int i = id; i < 2 * 172; i += NT) {
        int dir = i / 172, r = i % 172;
        float s = A.bih[dir][r] + A.bhh[dir][r];
        for (int k = 0; k < 43; ++k)
            s += A.wih[dir][r * 43 + k] * A.b_proj[k];
        g_b1[i] = s;
    }

    // ---- Layer-2 weights: 2 x 34 chunks x 176 x 4 (J=136) ----
    const int N2 = 2 * 34 * 176 * 4;
    for (int i = id; i < N2; i += NT) {
        int dir = i / (34 * 176 * 4);
        int rem = i % (34 * 176 * 4);
        int c = rem / (176 * 4);
        int row = (rem >> 2) % 176;
        int comp = rem & 3;
        int j = 4 * c + comp;
        int di = 2 + dir;
        float v = 0.f;
        if (row < 172) {
            if (j < 86)                 v = A.wih[di][row * 86 + j];
            else if (j >= 88 && j < 131) v = A.whh[di][row * 43 + (j - 88)];
        }
        g_W2[i] = v;
    }
    for (int i = id; i < 2 * 172; i += NT) {
        int dir = i / 172, r = i % 172;
        g_b2[i] = A.bih[2 + dir][r] + A.bhh[2 + dir][r];
    }
}

__device__ __forceinline__ float fsig(float x) {
    return __fdividef(1.f, 1.f + __expf(-x));
}
__device__ __forceinline__ float ftanh_(float x) {
    return 2.f * __fdividef(1.f, 1.f + __expf(-2.f * x)) - 1.f;
}
__device__ __forceinline__ void ffma2(ull& d, ull a, ull b) {
    asm("fma.rn.f32x2 %0, %1, %2, %0;" : "+l"(d) : "l"(a), "l"(b));
}
__device__ __forceinline__ float2 unpk(ull v) {
    float2 r;
    asm("mov.b64 {%0, %1}, %2;" : "=f"(r.x), "=f"(r.y) : "l"(v));
    return r;
}

// One block = 4 sequences (batch quad) x one direction. 352 threads.
// tid -> (row = tid>>1 in [0,176), jh = tid&1). Weights are loop-invariant and
// REGISTER-RESIDENT (loaded once before the loop: JC ulonglong2 per thread).
// Each thread accumulates the (even,odd) j-partials of its j-half for all 4
// sequences with fma.rn.f32x2; halves combined via shfl_xor(1).
template <int JC, int J, int HOFF, int INW, int LAYER>
__global__ __launch_bounds__(352) void lstm_kernel(const float* __restrict__ x_in) {
    __shared__ __align__(16) float sV[4][J];    // [seq][j]
    __shared__ __align__(16) float4 sG[176];    // [gate row] = 4 seqs

    const int tid = threadIdx.x;
    const int quad = blockIdx.x >> 1;
    const int dir = blockIdx.x & 1;
    const int b0 = quad * 4;
    const int row = tid >> 1;
    const int jh = tid & 1;

    const float* gWf = (LAYER == 1 ? g_W1 : g_W2);
    const ulonglong2* __restrict__ gw2 =
        (const ulonglong2*)gWf + ((size_t)dir * 2 * JC + jh * JC) * 176 + row;
    const float* gB = (LAYER == 1 ? g_b1 : g_b2) + dir * 172;
    const float bias = (row < 172) ? gB[row] : 0.f;

    // ---- Hoist loop-invariant weights into registers (once per kernel) ----
    ulonglong2 wreg[JC];
#pragma unroll
    for (int q = 0; q < JC; ++q) wreg[q] = gw2[q * 176];

    const float* in = (LAYER == 1 ? x_in : (const float*)g_y1);
    float* out = (LAYER == 1 ? g_y1 : g_y2);

    // Stagers: 4*INW threads, seq-major coalesced per sequence.
    const int sseq = tid / INW;
    const int sj = tid - sseq * INW;
    const bool stager = (tid < 4 * INW);
    const float* inme = in + (size_t)(b0 + (stager ? sseq : 0)) * TT * INW;

    // Cell/output: threads 0..171 -> (cr = tid>>2, cseq = tid&3)
    const int cr = tid >> 2;
    const int cseq = tid & 3;
    float* outme = out + (size_t)(b0 + cseq) * TT * 86 + dir * 43;
    float c = 0.f;

    // Zero v (padding + h0 = 0)
    for (int i = tid; i < 4 * J; i += 352) ((float*)sV)[i] = 0.f;

    float rin = 0.f;
    if (stager) rin = inme[(size_t)(dir ? TT - 1 : 0) * INW + sj];
    __syncthreads();

    for (int step = 0; step < TT; ++step) {
        const int t = dir ? (TT - 1 - step) : step;

        if (stager) sV[sseq][sj] = rin;
        float rnext = 0.f;
        if (stager && step + 1 < TT) {
            int tn = dir ? (TT - 2 - step) : (step + 1);
            rnext = inme[(size_t)tn * INW + sj];
        }
        __syncthreads();  // A: v (ext input + h) ready

        ull a0 = 0, a1 = 0, a2 = 0, a3 = 0;
#pragma unroll
        for (int q = 0; q < JC; ++q) {
            const ulonglong2 w = wreg[q];
            const int jb = (jh * JC + q) * 4;
            ulonglong2 v0 = *(const ulonglong2*)&sV[0][jb];
            ulonglong2 v1 = *(const ulonglong2*)&sV[1][jb];
            ulonglong2 v2 = *(const ulonglong2*)&sV[2][jb];
            ulonglong2 v3 = *(const ulonglong2*)&sV[3][jb];
            ffma2(a0, w.x, v0.x); ffma2(a0, w.y, v0.y);
            ffma2(a1, w.x, v1.x); ffma2(a1, w.y, v1.y);
            ffma2(a2, w.x, v2.x); ffma2(a2, w.y, v2.y);
            ffma2(a3, w.x, v3.x); ffma2(a3, w.y, v3.y);
        }
        float2 p;
        p = unpk(a0); float z0 = p.x + p.y;
        p = unpk(a1); float z1 = p.x + p.y;
        p = unpk(a2); float z2 = p.x + p.y;
        p = unpk(a3); float z3 = p.x + p.y;
        z0 += __shfl_xor_sync(0xffffffffu, z0, 1);
        z1 += __shfl_xor_sync(0xffffffffu, z1, 1);
        z2 += __shfl_xor_sync(0xffffffffu, z2, 1);
        z3 += __shfl_xor_sync(0xffffffffu, z3, 1);

        if (jh == 0 && row < 172) {
            z0 += bias; z1 += bias; z2 += bias; z3 += bias;
            const bool isg = (row >= 86) && (row < 129);  // g gate -> tanh
            float4 g;
            g.x = isg ? ftanh_(z0) : fsig(z0);
            g.y = isg ? ftanh_(z1) : fsig(z1);
            g.z = isg ? ftanh_(z2) : fsig(z2);
            g.w = isg ? ftanh_(z3) : fsig(z3);
            sG[row] = g;
        }
        __syncthreads();  // B: gates ready

        if (tid < 172) {
            const float* gf = (const float*)sG;
            float iv = gf[cr * 4 + cseq];
            float fv = gf[(43 + cr) * 4 + cseq];
            float gv = gf[(86 + cr) * 4 + cseq];
            float ov = gf[(129 + cr) * 4 + cseq];
            c = fv * c + iv * gv;
            float h = ov * ftanh_(c);
            sV[cseq][HOFF + cr] = h;
            outme[(size_t)t * 86 + cr] = h;
        }
        rin = rnext;
    }
}

// ---------------- Dense head: 64 rows per block (35 KB smem) ----------------
__global__ __launch_bounds__(64) void dense_kernel(
    const float* __restrict__ wd1, const float* __restrict__ bd1,
    const float* __restrict__ wd2, const float* __restrict__ bd2,
    const float* __restrict__ wo, const float* __restrict__ bo,
    float* __restrict__ outp) {
    __shared__ __align__(16) float s_w1[30 * 86];
    __shared__ __align__(16) float s_w2[20 * 30];
    __shared__ float s_b1[30], s_b2[20], s_wo[20];
    __shared__ __align__(16) float s_y[64 * 86];

    int tid = threadIdx.x;
    for (int i = tid; i < 30 * 86; i += 64) s_w1[i] = wd1[i];
    for (int i = tid; i < 20 * 30; i += 64) s_w2[i] = wd2[i];
    if (tid < 30) s_b1[tid] = bd1[tid];
    if (tid < 20) { s_b2[tid] = bd2[tid]; s_wo[tid] = wo[tid]; }

    size_t base = (size_t)blockIdx.x * 64;
    for (int i = tid; i < (64 * 86) / 2; i += 64)
        ((float2*)s_y)[i] = ((const float2*)(g_y2 + base * 86))[i];
    __syncthreads();

    const float* v = s_y + tid * 86;
    float h1[30];
#pragma unroll
    for (int k = 0; k < 30; ++k) h1[k] = s_b1[k];
    for (int cc = 0; cc < 86; ++cc) {
        float vv = v[cc];
#pragma unroll
        for (int k = 0; k < 30; ++k) h1[k] = fmaf(s_w1[k * 86 + cc], vv, h1[k]);
    }
    float h2[20];
#pragma unroll
    for (int k = 0; k < 20; ++k) h2[k] = s_b2[k];
#pragma unroll
    for (int cc = 0; cc < 30; ++cc) {
        float vv = fmaxf(h1[cc], 0.f);
#pragma unroll
        for (int k = 0; k < 20; ++k) h2[k] = fmaf(s_w2[k * 30 + cc], vv, h2[k]);
    }
    float o = bo[0];
#pragma unroll
    for (int k = 0; k < 20; ++k) o = fmaf(s_wo[k], fmaxf(h2[k], 0.f), o);
    outp[base + tid] = o;
}

extern "C" void kernel_launch(void* const* d_in, const int* in_sizes, int n_in,
                              void* d_out, int out_size) {
    const float* x = (const float*)d_in[0];
    PrepArgs A;
    A.w_proj = (const float*)d_in[1];
    A.b_proj = (const float*)d_in[2];
    for (int g = 0; g < 4; ++g) {
        A.wih[g] = (const float*)d_in[3 + g * 4 + 0];
        A.whh[g] = (const float*)d_in[3 + g * 4 + 1];
        A.bih[g] = (const float*)d_in[3 + g * 4 + 2];
        A.bhh[g] = (const float*)d_in[3 + g * 4 + 3];
    }
    const float* wd1 = (const float*)d_in[19];
    const float* bd1 = (const float*)d_in[20];
    const float* wd2 = (const float*)d_in[21];
    const float* bd2 = (const float*)d_in[22];
    const float* wo  = (const float*)d_in[23];
    const float* bo  = (const float*)d_in[24];

    prep_kernel<<<64, 256>>>(A);
    lstm_kernel<7, 56, 8, 8, 1><<<128, 352>>>(x);            // layer 1 (proj folded)
    lstm_kernel<17, 136, 88, 86, 2><<<128, 352>>>(nullptr);  // layer 2
    dense_kernel<<<(BB * TT) / 64, 64>>>(wd1, bd1, wd2, bd2, wo, bo, (float*)d_out);
}